// round 2
// baseline (speedup 1.0000x reference)
#include <cuda_runtime.h>

#define F_IN  512
#define F_HID 128
#define F_OUT 64
#define N_MAX 100000

// ---------------- scratch (device globals; no allocation allowed) ----------
__device__ int   g_is64;
__device__ int   g_deg [N_MAX];
__device__ float g_dinv[N_MAX];
__device__ float g_h1  [(size_t)N_MAX * F_HID];   // layer1 GEMM out, later reused as layer2 input
__device__ float g_agg1[(size_t)N_MAX * F_HID];   // layer1 aggregation
__device__ float g_h2  [(size_t)N_MAX * F_OUT];   // layer2 GEMM out

// ---------------- edge-index dtype detection --------------------------------
// int64 non-negative values < 2^31  =>  every odd 32-bit word is 0.
// int32 node ids in [0,1e5)         =>  2048 consecutive odd words all-zero ~ impossible.
__global__ void detect_kernel(const int* __restrict__ w, int n_words) {
    __shared__ int any;
    if (threadIdx.x == 0) any = 0;
    __syncthreads();
    int lim = min(2048, n_words / 2);
    for (int i = threadIdx.x; i < lim; i += blockDim.x)
        if (w[2 * i + 1] != 0) any = 1;   // benign race
    __syncthreads();
    if (threadIdx.x == 0) g_is64 = (any == 0);
}

__device__ __forceinline__ long long edge_at(const void* ei, long long idx) {
    if (g_is64) return ((const long long*)ei)[idx];
    return (long long)((const int*)ei)[idx];
}

// ---------------- degree / normalization ------------------------------------
__global__ void deg_init(int N) {
    int i = blockIdx.x * blockDim.x + threadIdx.x;
    if (i < N) g_deg[i] = 1;              // self-loop
}
__global__ void deg_count(const void* __restrict__ ei, int E) {
    int e = blockIdx.x * blockDim.x + threadIdx.x;
    if (e >= E) return;
    int dst = (int)edge_at(ei, (long long)E + e);
    atomicAdd(&g_deg[dst], 1);
}
__global__ void dinv_kernel(int N) {
    int i = blockIdx.x * blockDim.x + threadIdx.x;
    if (i < N) g_dinv[i] = rsqrtf((float)g_deg[i]);
}

// ---------------- tiled SGEMM  C[M,N] = A[M,K] @ B[K,N] ----------------------
template <int BM, int BN, int BK, int TM, int TN>
__global__ __launch_bounds__(256) void sgemm(const float* __restrict__ A,
                                             const float* __restrict__ B,
                                             float* __restrict__ C,
                                             int M, int N, int K) {
    __shared__ float As[BK][BM + 4];
    __shared__ float Bs[BK][BN];
    const int tid = threadIdx.x;
    const int bm0 = blockIdx.x * BM;
    const int bn0 = blockIdx.y * BN;
    const int tx  = tid % (BN / TN);
    const int ty  = tid / (BN / TN);

    float acc[TM][TN];
#pragma unroll
    for (int i = 0; i < TM; i++)
#pragma unroll
        for (int j = 0; j < TN; j++) acc[i][j] = 0.f;

    for (int k0 = 0; k0 < K; k0 += BK) {
        // A tile (transposed into smem)
#pragma unroll
        for (int i = tid; i < BM * BK / 4; i += 256) {
            int idx = i * 4;
            int r = idx / BK, c = idx % BK;
            float4 v = make_float4(0.f, 0.f, 0.f, 0.f);
            int gr = bm0 + r;
            if (gr < M) v = *(const float4*)(A + (size_t)gr * K + k0 + c);
            As[c + 0][r] = v.x; As[c + 1][r] = v.y;
            As[c + 2][r] = v.z; As[c + 3][r] = v.w;
        }
        // B tile
#pragma unroll
        for (int i = tid; i < BK * BN / 4; i += 256) {
            int idx = i * 4;
            int r = idx / BN, c = idx % BN;
            *(float4*)&Bs[r][c] = *(const float4*)(B + (size_t)(k0 + r) * N + bn0 + c);
        }
        __syncthreads();
#pragma unroll
        for (int k = 0; k < BK; k++) {
            float a[TM], b[TN];
#pragma unroll
            for (int i = 0; i < TM; i++) a[i] = As[k][ty * TM + i];
#pragma unroll
            for (int j = 0; j < TN; j++) b[j] = Bs[k][tx * TN + j];
#pragma unroll
            for (int i = 0; i < TM; i++)
#pragma unroll
                for (int j = 0; j < TN; j++) acc[i][j] += a[i] * b[j];
        }
        __syncthreads();
    }
#pragma unroll
    for (int i = 0; i < TM; i++) {
        int gr = bm0 + ty * TM + i;
        if (gr < M) {
#pragma unroll
            for (int j = 0; j < TN; j += 4)
                *(float4*)(C + (size_t)gr * N + bn0 + tx * TN + j) =
                    make_float4(acc[i][j], acc[i][j + 1], acc[i][j + 2], acc[i][j + 3]);
        }
    }
}

// ---------------- self-loop init / epilogues ---------------------------------
__global__ void self_init1(int N) {
    int i = blockIdx.x * blockDim.x + threadIdx.x;
    if (i >= N * F_HID) return;
    float d = g_dinv[i / F_HID];
    g_agg1[i] = g_h1[i] * d * d;
}
__global__ void bias_relu(const float* __restrict__ b1, int N) {
    int i = blockIdx.x * blockDim.x + threadIdx.x;
    if (i >= N * F_HID) return;
    float v = g_agg1[i] + b1[i & (F_HID - 1)];
    g_h1[i] = v > 0.f ? v : 0.f;       // reuse g_h1 as layer-2 input
}
__global__ void self_init2(const float* __restrict__ b2, float* __restrict__ out, int N) {
    int i = blockIdx.x * blockDim.x + threadIdx.x;
    if (i >= N * F_OUT) return;
    float d = g_dinv[i / F_OUT];
    out[i] = g_h2[i] * d * d + b2[i & (F_OUT - 1)];
}

// ---------------- edge scatter: warp per edge --------------------------------
template <int F>
__global__ __launch_bounds__(256) void scatter_add(const void* __restrict__ ei, int E,
                                                   const float* __restrict__ h,
                                                   float* __restrict__ out) {
    long long e = (long long)blockIdx.x * (blockDim.x >> 5) + (threadIdx.x >> 5);
    if (e >= E) return;
    int lane = threadIdx.x & 31;
    long long src = edge_at(ei, e);
    long long dst = edge_at(ei, (long long)E + e);
    float norm = g_dinv[src] * g_dinv[dst];
    const float* hrow = h + src * F;
    float* orow = out + dst * F;
    if (F == 128) {
        float4 v = ((const float4*)hrow)[lane];
        int b = lane * 4;
        atomicAdd(orow + b + 0, v.x * norm);
        atomicAdd(orow + b + 1, v.y * norm);
        atomicAdd(orow + b + 2, v.z * norm);
        atomicAdd(orow + b + 3, v.w * norm);
    } else {  // F == 64
        float2 v = ((const float2*)hrow)[lane];
        int b = lane * 2;
        atomicAdd(orow + b + 0, v.x * norm);
        atomicAdd(orow + b + 1, v.y * norm);
    }
}

// ---------------- launch -----------------------------------------------------
extern "C" void kernel_launch(void* const* d_in, const int* in_sizes, int n_in,
                              void* d_out, int out_size) {
    const float* x  = (const float*)d_in[0];
    const void*  ei = d_in[1];
    const float* W1 = (const float*)d_in[2];
    const float* b1 = (const float*)d_in[3];
    const float* W2 = (const float*)d_in[4];
    const float* b2 = (const float*)d_in[5];
    float* out = (float*)d_out;

    const int N = in_sizes[0] / F_IN;
    const int E = in_sizes[1] / 2;

    float *h1p, *agg1p, *h2p;
    cudaGetSymbolAddress((void**)&h1p,   g_h1);
    cudaGetSymbolAddress((void**)&agg1p, g_agg1);
    cudaGetSymbolAddress((void**)&h2p,   g_h2);

    detect_kernel<<<1, 256>>>((const int*)ei, in_sizes[1]);
    deg_init<<<(N + 255) / 256, 256>>>(N);
    deg_count<<<(E + 255) / 256, 256>>>(ei, E);
    dinv_kernel<<<(N + 255) / 256, 256>>>(N);

    // Layer 1: h1 = x @ W1
    sgemm<128, 128, 16, 8, 8><<<dim3((N + 127) / 128, 1), 256>>>(x, W1, h1p, N, F_HID, F_IN);
    self_init1<<<(N * F_HID + 255) / 256, 256>>>(N);
    scatter_add<F_HID><<<(E + 7) / 8, 256>>>(ei, E, h1p, agg1p);
    bias_relu<<<(N * F_HID + 255) / 256, 256>>>(b1, N);

    // Layer 2: h2 = relu_out @ W2
    sgemm<128, 64, 16, 8, 4><<<dim3((N + 127) / 128, 1), 256>>>(h1p, W2, h2p, N, F_OUT, F_HID);
    self_init2<<<(N * F_OUT + 255) / 256, 256>>>(b2, out, N);
    scatter_add<F_OUT><<<(E + 7) / 8, 256>>>(ei, E, h2p, out);
}

// round 3
// speedup vs baseline: 2.6525x; 2.6525x over previous
#include <cuda_runtime.h>
#include <stdint.h>

#define F_IN  512
#define F_HID 128
#define F_OUT 64
#define N_MAX 100000
#define E_MAX 1600000

// ---------------- scratch (device globals; no allocation allowed) ----------
__device__ int   g_is64;
__device__ int   g_deg   [N_MAX];
__device__ int   g_cursor[N_MAX];
__device__ int   g_off   [N_MAX + 1];
__device__ float g_dinv  [N_MAX];
__device__ int   g_csr_src[E_MAX];
__device__ float g_csr_w  [E_MAX];
__device__ float g_h1  [(size_t)N_MAX * F_HID];   // GEMM1 out
__device__ float g_a1  [(size_t)N_MAX * F_HID];   // layer1 aggregated (GEMM2 input)
__device__ float g_h2  [(size_t)N_MAX * F_OUT];   // GEMM2 out

// ---------------- edge-index dtype detection --------------------------------
// int64 non-negative values < 2^31  =>  every odd 32-bit word is 0.
__global__ void detect_kernel(const int* __restrict__ w, int n_words) {
    __shared__ int any;
    if (threadIdx.x == 0) any = 0;
    __syncthreads();
    int lim = min(2048, n_words / 2);
    for (int i = threadIdx.x; i < lim; i += blockDim.x)
        if (w[2 * i + 1] != 0) any = 1;   // benign race
    __syncthreads();
    if (threadIdx.x == 0) g_is64 = (any == 0);
}

__device__ __forceinline__ int edge_at(const void* ei, long long idx) {
    if (g_is64) return (int)((const long long*)ei)[idx];
    return ((const int*)ei)[idx];
}

// ---------------- degree / normalization / CSR build -------------------------
__global__ void deg_init(int N) {
    int i = blockIdx.x * blockDim.x + threadIdx.x;
    if (i < N) { g_deg[i] = 1; g_cursor[i] = 0; }   // self-loop counted
}
__global__ void deg_count(const void* __restrict__ ei, int E) {
    int e = blockIdx.x * blockDim.x + threadIdx.x;
    if (e >= E) return;
    atomicAdd(&g_deg[edge_at(ei, (long long)E + e)], 1);
}
__global__ void dinv_kernel(int N) {
    int i = blockIdx.x * blockDim.x + threadIdx.x;
    if (i < N) g_dinv[i] = rsqrtf((float)g_deg[i]);
}

// single-block exclusive scan of (deg-1) -> g_off
__global__ void scan_kernel(int N, int E) {
    __shared__ int sh[1024];
    int tid = threadIdx.x;
    int chunk = (N + 1023) >> 10;
    int st = tid * chunk, en = min(st + chunk, N);
    int s = 0;
    for (int i = st; i < en; i++) s += g_deg[i] - 1;
    sh[tid] = s;
    __syncthreads();
    for (int off = 1; off < 1024; off <<= 1) {
        int v = (tid >= off) ? sh[tid - off] : 0;
        __syncthreads();
        sh[tid] += v;
        __syncthreads();
    }
    int base = tid ? sh[tid - 1] : 0;
    for (int i = st; i < en; i++) { g_off[i] = base; base += g_deg[i] - 1; }
    if (tid == 0) g_off[N] = E;
}

__global__ void place_kernel(const void* __restrict__ ei, int E) {
    int e = blockIdx.x * blockDim.x + threadIdx.x;
    if (e >= E) return;
    int src = edge_at(ei, e);
    int dst = edge_at(ei, (long long)E + e);
    int pos = g_off[dst] + atomicAdd(&g_cursor[dst], 1);
    g_csr_src[pos] = src;
    g_csr_w[pos]   = g_dinv[src] * g_dinv[dst];
}

// ---------------- TF32 tensor-core GEMM --------------------------------------
__device__ __forceinline__ uint32_t tf32_of(float x) {
    uint32_t u;
    asm("cvt.rna.tf32.f32 %0, %1;" : "=r"(u) : "f"(x));
    return u;
}
__device__ __forceinline__ void mma_tf32(float* d, const uint32_t* a, const uint32_t* b) {
    asm volatile(
        "mma.sync.aligned.m16n8k8.row.col.f32.tf32.tf32.f32 "
        "{%0,%1,%2,%3}, {%4,%5,%6,%7}, {%8,%9}, {%0,%1,%2,%3};"
        : "+f"(d[0]), "+f"(d[1]), "+f"(d[2]), "+f"(d[3])
        : "r"(a[0]), "r"(a[1]), "r"(a[2]), "r"(a[3]), "r"(b[0]), "r"(b[1]));
}

// C[M,N] = A[M,K] @ B[K,N], row-major. 256 threads. N % BN == 0, K % BK == 0.
template <int BM, int BN, int BK, int WM, int WN>
__global__ __launch_bounds__(256) void mma_gemm(const float* __restrict__ A,
                                                const float* __restrict__ B,
                                                float* __restrict__ C,
                                                int M, int N, int K) {
    constexpr int WARPS_N = BN / WN;
    constexpr int MI = WM / 16;
    constexpr int NI = WN / 8;
    constexpr int KS = BK / 8;
    constexpr int APAD = 4;   // bank spread: (4r + c) mod 32 distinct
    constexpr int BPAD = 8;   // bank spread: (8r + g) mod 32 distinct

    __shared__ uint32_t As[BM][BK + APAD];
    __shared__ uint32_t Bs[BK][BN + BPAD];

    const int tid  = threadIdx.x;
    const int lane = tid & 31;
    const int w    = tid >> 5;
    const int wm   = w / WARPS_N;
    const int wn   = w % WARPS_N;
    const int bm0  = blockIdx.x * BM;
    const int bn0  = blockIdx.y * BN;

    float acc[MI][NI][4];
#pragma unroll
    for (int i = 0; i < MI; i++)
#pragma unroll
        for (int j = 0; j < NI; j++)
#pragma unroll
            for (int k = 0; k < 4; k++) acc[i][j][k] = 0.f;

    for (int k0 = 0; k0 < K; k0 += BK) {
        // A tile -> smem (tf32-rounded)
#pragma unroll
        for (int i = tid; i < BM * BK / 4; i += 256) {
            int r  = i / (BK / 4);
            int c4 = (i % (BK / 4)) * 4;
            float4 v = make_float4(0.f, 0.f, 0.f, 0.f);
            int gr = bm0 + r;
            if (gr < M) v = *(const float4*)(A + (size_t)gr * K + k0 + c4);
            As[r][c4 + 0] = tf32_of(v.x); As[r][c4 + 1] = tf32_of(v.y);
            As[r][c4 + 2] = tf32_of(v.z); As[r][c4 + 3] = tf32_of(v.w);
        }
        // B tile -> smem (tf32-rounded)
#pragma unroll
        for (int i = tid; i < BK * BN / 4; i += 256) {
            int r  = i / (BN / 4);
            int c4 = (i % (BN / 4)) * 4;
            float4 v = *(const float4*)(B + (size_t)(k0 + r) * N + bn0 + c4);
            Bs[r][c4 + 0] = tf32_of(v.x); Bs[r][c4 + 1] = tf32_of(v.y);
            Bs[r][c4 + 2] = tf32_of(v.z); Bs[r][c4 + 3] = tf32_of(v.w);
        }
        __syncthreads();

#pragma unroll
        for (int ks = 0; ks < KS; ks++) {
            uint32_t af[MI][4], bf[NI][2];
            const int c = ks * 8 + (lane & 3);
#pragma unroll
            for (int mi = 0; mi < MI; mi++) {
                int r0 = wm * WM + mi * 16 + (lane >> 2);
                af[mi][0] = As[r0][c];     af[mi][1] = As[r0 + 8][c];
                af[mi][2] = As[r0][c + 4]; af[mi][3] = As[r0 + 8][c + 4];
            }
            const int br = ks * 8 + (lane & 3);
#pragma unroll
            for (int ni = 0; ni < NI; ni++) {
                int n0 = wn * WN + ni * 8 + (lane >> 2);
                bf[ni][0] = Bs[br][n0];
                bf[ni][1] = Bs[br + 4][n0];
            }
#pragma unroll
            for (int mi = 0; mi < MI; mi++)
#pragma unroll
                for (int ni = 0; ni < NI; ni++)
                    mma_tf32(acc[mi][ni], af[mi], bf[ni]);
        }
        __syncthreads();
    }

    // store
#pragma unroll
    for (int mi = 0; mi < MI; mi++) {
#pragma unroll
        for (int ni = 0; ni < NI; ni++) {
            int r0 = bm0 + wm * WM + mi * 16 + (lane >> 2);
            int cc = bn0 + wn * WN + ni * 8 + (lane & 3) * 2;
            if (r0 < M)
                *(float2*)(C + (size_t)r0 * N + cc) = make_float2(acc[mi][ni][0], acc[mi][ni][1]);
            if (r0 + 8 < M)
                *(float2*)(C + (size_t)(r0 + 8) * N + cc) = make_float2(acc[mi][ni][2], acc[mi][ni][3]);
        }
    }
}

// ---------------- gather aggregation (warp per node) --------------------------
template <int F, bool RELU>
__global__ __launch_bounds__(256) void gather_agg(const float* __restrict__ h,
                                                  const float* __restrict__ bias,
                                                  float* __restrict__ outp, int N) {
    int node = blockIdx.x * (blockDim.x >> 5) + (threadIdx.x >> 5);
    if (node >= N) return;
    int lane = threadIdx.x & 31;
    int e = g_off[node], e1 = g_off[node + 1];
    float dn = g_dinv[node];
    float sw = dn * dn;

    if (F == 128) {
        const float4* hp = (const float4*)h;
        float4 acc = hp[(size_t)node * 32 + lane];
        acc.x *= sw; acc.y *= sw; acc.z *= sw; acc.w *= sw;
        for (; e + 4 <= e1; e += 4) {
            int s0 = g_csr_src[e], s1 = g_csr_src[e + 1];
            int s2 = g_csr_src[e + 2], s3 = g_csr_src[e + 3];
            float w0 = g_csr_w[e], w1 = g_csr_w[e + 1];
            float w2 = g_csr_w[e + 2], w3 = g_csr_w[e + 3];
            float4 v0 = hp[(size_t)s0 * 32 + lane];
            float4 v1 = hp[(size_t)s1 * 32 + lane];
            float4 v2 = hp[(size_t)s2 * 32 + lane];
            float4 v3 = hp[(size_t)s3 * 32 + lane];
            acc.x += w0 * v0.x + w1 * v1.x + w2 * v2.x + w3 * v3.x;
            acc.y += w0 * v0.y + w1 * v1.y + w2 * v2.y + w3 * v3.y;
            acc.z += w0 * v0.z + w1 * v1.z + w2 * v2.z + w3 * v3.z;
            acc.w += w0 * v0.w + w1 * v1.w + w2 * v2.w + w3 * v3.w;
        }
        for (; e < e1; e++) {
            int s = g_csr_src[e];
            float wv = g_csr_w[e];
            float4 v = hp[(size_t)s * 32 + lane];
            acc.x += wv * v.x; acc.y += wv * v.y; acc.z += wv * v.z; acc.w += wv * v.w;
        }
        float4 b = ((const float4*)bias)[lane];
        acc.x += b.x; acc.y += b.y; acc.z += b.z; acc.w += b.w;
        if (RELU) {
            acc.x = fmaxf(acc.x, 0.f); acc.y = fmaxf(acc.y, 0.f);
            acc.z = fmaxf(acc.z, 0.f); acc.w = fmaxf(acc.w, 0.f);
        }
        ((float4*)outp)[(size_t)node * 32 + lane] = acc;
    } else {  // F == 64
        const float2* hp = (const float2*)h;
        float2 acc = hp[(size_t)node * 32 + lane];
        acc.x *= sw; acc.y *= sw;
        for (; e + 4 <= e1; e += 4) {
            int s0 = g_csr_src[e], s1 = g_csr_src[e + 1];
            int s2 = g_csr_src[e + 2], s3 = g_csr_src[e + 3];
            float w0 = g_csr_w[e], w1 = g_csr_w[e + 1];
            float w2 = g_csr_w[e + 2], w3 = g_csr_w[e + 3];
            float2 v0 = hp[(size_t)s0 * 32 + lane];
            float2 v1 = hp[(size_t)s1 * 32 + lane];
            float2 v2 = hp[(size_t)s2 * 32 + lane];
            float2 v3 = hp[(size_t)s3 * 32 + lane];
            acc.x += w0 * v0.x + w1 * v1.x + w2 * v2.x + w3 * v3.x;
            acc.y += w0 * v0.y + w1 * v1.y + w2 * v2.y + w3 * v3.y;
        }
        for (; e < e1; e++) {
            int s = g_csr_src[e];
            float wv = g_csr_w[e];
            float2 v = hp[(size_t)s * 32 + lane];
            acc.x += wv * v.x; acc.y += wv * v.y;
        }
        float2 b = ((const float2*)bias)[lane];
        acc.x += b.x; acc.y += b.y;
        if (RELU) { acc.x = fmaxf(acc.x, 0.f); acc.y = fmaxf(acc.y, 0.f); }
        ((float2*)outp)[(size_t)node * 32 + lane] = acc;
    }
}

// ---------------- launch -----------------------------------------------------
extern "C" void kernel_launch(void* const* d_in, const int* in_sizes, int n_in,
                              void* d_out, int out_size) {
    const float* x  = (const float*)d_in[0];
    const void*  ei = d_in[1];
    const float* W1 = (const float*)d_in[2];
    const float* b1 = (const float*)d_in[3];
    const float* W2 = (const float*)d_in[4];
    const float* b2 = (const float*)d_in[5];
    float* out = (float*)d_out;

    const int N = in_sizes[0] / F_IN;
    const int E = in_sizes[1] / 2;

    float *h1p, *a1p, *h2p;
    cudaGetSymbolAddress((void**)&h1p, g_h1);
    cudaGetSymbolAddress((void**)&a1p, g_a1);
    cudaGetSymbolAddress((void**)&h2p, g_h2);

    detect_kernel<<<1, 256>>>((const int*)ei, in_sizes[1]);
    deg_init<<<(N + 255) / 256, 256>>>(N);
    deg_count<<<(E + 255) / 256, 256>>>(ei, E);
    dinv_kernel<<<(N + 255) / 256, 256>>>(N);
    scan_kernel<<<1, 1024>>>(N, E);
    place_kernel<<<(E + 255) / 256, 256>>>(ei, E);

    // Layer 1: h1 = x @ W1 ; a1 = relu(A_norm h1 + b1)
    mma_gemm<128, 128, 32, 64, 32><<<dim3((N + 127) / 128, F_HID / 128), 256>>>(
        x, W1, h1p, N, F_HID, F_IN);
    gather_agg<F_HID, true><<<(N + 7) / 8, 256>>>(h1p, b1, a1p, N);

    // Layer 2: h2 = a1 @ W2 ; out = A_norm h2 + b2
    mma_gemm<128, 64, 32, 32, 32><<<dim3((N + 127) / 128, F_OUT / 64), 256>>>(
        a1p, W2, h2p, N, F_OUT, F_HID);
    gather_agg<F_OUT, false><<<(N + 7) / 8, 256>>>(h2p, b2, out, N);
}